// round 5
// baseline (speedup 1.0000x reference)
#include <cuda_runtime.h>
#include <math.h>

#define NT 512
#define RPB 8
#define NBLK 128
#define KC 32

typedef unsigned long long ull;

// ---------------- device scratch ----------------
__device__ float g_W0cat[152 * 512];   // [k][g]: rows 0..23 Wih0^T, 24..151 Whh0^T
__device__ float g_W1cat[256 * 512];   // [k][g]: rows 0..127 Wih1^T, 128..255 Whh1^T
__device__ float g_b0[512];
__device__ float g_b1[512];
__device__ float g_W1T[184 * 128];     // [k][u]
__device__ float g_W2s[128 * 128];     // [u][v] = W2[v][u]
__device__ float g_A1t[100 * 128];
__device__ float g_cy[100];
__device__ float g_ce[100];

// ---------------- prologue ----------------
__global__ void prologue_kernel(const float* __restrict__ W_ih0, const float* __restrict__ W_hh0,
                                const float* __restrict__ b_ih0, const float* __restrict__ b_hh0,
                                const float* __restrict__ W_ih1, const float* __restrict__ W_hh1,
                                const float* __restrict__ b_ih1, const float* __restrict__ b_hh1,
                                const float* __restrict__ W1,    const float* __restrict__ W2) {
    int tid = blockIdx.x * blockDim.x + threadIdx.x;
    int nth = gridDim.x * blockDim.x;

    for (int i = tid; i < 24 * 512; i += nth) {
        int k = i >> 9, g = i & 511;
        g_W0cat[i] = W_ih0[g * 24 + k];
    }
    for (int i = tid; i < 128 * 512; i += nth) {
        int k = i >> 9, g = i & 511;
        g_W0cat[(24 + k) * 512 + g]  = W_hh0[g * 128 + k];
        g_W1cat[k * 512 + g]         = W_ih1[g * 128 + k];
        g_W1cat[(128 + k) * 512 + g] = W_hh1[g * 128 + k];
    }
    for (int i = tid; i < 512; i += nth) {
        g_b0[i] = b_ih0[i] + b_hh0[i];
        g_b1[i] = b_ih1[i] + b_hh1[i];
    }
    for (int i = tid; i < 184 * 128; i += nth) {
        int k = i >> 7, u = i & 127;
        g_W1T[i] = W1[u * 184 + k];
    }
    for (int i = tid; i < 128 * 128; i += nth) {
        int u = i >> 7, v = i & 127;
        g_W2s[i] = W2[v * 128 + u];
    }
    for (int i = tid; i < 100 * 128; i += nth) {
        int t = i >> 7, u = i & 127;
        float acc = 0.f;
        #pragma unroll
        for (int j = 0; j < 8; j++) {
            float f = expf(-logf(10000.0f) * (float)j / 8.0f);
            float a = (float)t * f;
            acc += W1[u * 184 + 152 + j] * cosf(a);
            acc += W1[u * 184 + 160 + j] * sinf(a);
        }
        g_A1t[i] = acc;
    }
    if (tid == 0) {
        float ab = 1.0f;
        for (int t = 0; t < 100; t++) {
            float beta  = 1e-4f + (0.02f - 1e-4f) * (float)t / 99.0f;
            float alpha = 1.0f - beta;
            ab *= alpha;
            if (t == 0) {
                float p = sqrtf(ab) + 1e-8f;
                g_cy[0] = 1.0f / p;
                g_ce[0] = sqrtf(1.0f - ab) / p;
            } else {
                float inv = 1.0f / (sqrtf(alpha) + 1e-8f);
                g_cy[t] = inv;
                g_ce[t] = beta / (sqrtf(1.0f - ab) + 1e-8f) * inv;
            }
        }
    }
}

// ---------------- fast math helpers ----------------
__device__ __forceinline__ float sigf(float x) {
    float xc = fminf(fmaxf(x, -30.f), 30.f);
    return __fdividef(1.0f, 1.0f + __expf(-xc));
}
__device__ __forceinline__ float tanhf_fast(float x) {
    float xc = fminf(fmaxf(x, -15.f), 15.f);
    float e = __expf(2.0f * xc);
    return __fdividef(e - 1.0f, e + 1.0f);
}
__device__ __forceinline__ void ffma2(ull &d, ull a, ull b) {
    asm("fma.rn.f32x2 %0, %1, %2, %0;" : "+l"(d) : "l"(a), "l"(b));
}
__device__ __forceinline__ ull dup2(float x) {
    ull r;
    asm("mov.b64 %0, {%1, %1};" : "=l"(r) : "f"(x));
    return r;
}
__device__ __forceinline__ ull pack2(float lo, float hi) {
    ull r;
    asm("mov.b64 %0, {%1, %2};" : "=l"(r) : "f"(lo), "f"(hi));
    return r;
}
__device__ __forceinline__ float2 unpack2(ull v) {
    float2 r;
    asm("mov.b64 {%0, %1}, %2;" : "=f"(r.x), "=f"(r.y) : "l"(v));
    return r;
}

// ---------------- smem layout (floats) ----------------
#define SM_XV     0        // [280][8]: rows 0..7 x, 8..23 emb, 24..151 h0, 152..279 h1
#define SM_GATES  2240     // [8][512]
#define SM_STAGE  6336     // 2 x (KC*512) = 32768
#define SM_B0     39104    // 512
#define SM_B1     39616    // 512
#define SM_EMBR   40128    // [8][16]
#define SM_EMBT   40256    // [16][8]
#define SM_MH1    40384    // [128][8]
#define SM_A1     41408    // 12800
#define SM_XFT    54208    // [6][8]
#define SM_HES    54256    // 16
#define SM_CY     54272    // 100
#define SM_CE     54372    // 100
#define SM_WPART  54472    // [16][8]
#define SM_TOTAL  54600
#define SMEM_BYTES (SM_TOTAL * 4)

// ---------------- staging helper ----------------
__device__ __forceinline__ void stage_chunk(float* sdst, const float* __restrict__ gsrc, int nf4) {
    unsigned sbase = (unsigned)__cvta_generic_to_shared(sdst);
    for (int i = threadIdx.x; i < nf4; i += NT) {
        asm volatile("cp.async.cg.shared.global [%0], [%1], 16;\n"
                     :: "r"(sbase + i * 16), "l"(gsrc + i * 4));
    }
    asm volatile("cp.async.commit_group;\n" ::: "memory");
}

// stream position s (0..12): chunks of [W0cat(152) ; W1cat(256)]
__device__ __forceinline__ void stage_stream(int s, float* stgbuf) {
    const float* src;
    int kc;
    if (s < 5) { src = g_W0cat + s * KC * 512; kc = (s == 4) ? 24 : 32; }
    else       { src = g_W1cat + (s - 5) * KC * 512; kc = 32; }
    stage_chunk(stgbuf, src, kc * 128);
}

// ---------------- main fused kernel ----------------
__global__ __launch_bounds__(NT, 1)
void fused_kernel(const float* __restrict__ x_hist, const float* __restrict__ x_future,
                  const float* __restrict__ y0, const int* __restrict__ turb_idx,
                  const float* __restrict__ init_noise, const float* __restrict__ turb_emb,
                  const float* __restrict__ b1m, const float* __restrict__ b2m,
                  const float* __restrict__ W3, const float* __restrict__ b3p,
                  float* __restrict__ out) {
    extern __shared__ float sm[];
    float* xv    = sm + SM_XV;
    float* gates = sm + SM_GATES;
    float* stg   = sm + SM_STAGE;
    float* b0s   = sm + SM_B0;
    float* b1s   = sm + SM_B1;
    float* embr  = sm + SM_EMBR;
    float* embT  = sm + SM_EMBT;
    float* mh1   = sm + SM_MH1;
    float* a1s   = sm + SM_A1;
    float* xfT   = sm + SM_XFT;
    float* hes   = sm + SM_HES;
    float* cys   = sm + SM_CY;
    float* ces   = sm + SM_CE;
    float* wpart = sm + SM_WPART;

    const int tid  = threadIdx.x;
    const int brow = blockIdx.x * RPB;

    // ---- init ----
    for (int i = tid; i < 2048; i += NT) xv[192 + i] = 0.0f;   // h0, h1 = 0
    for (int i = tid; i < 512; i += NT) { b0s[i] = g_b0[i]; b1s[i] = g_b1[i]; }
    for (int i = tid; i < 12800; i += NT) a1s[i] = g_A1t[i];
    if (tid < 128) {
        int r = tid >> 4, k = tid & 15;
        embr[r * 16 + k] = turb_emb[turb_idx[brow + r] * 16 + k];
    }
    if (tid < 100) { cys[tid] = g_cy[tid]; ces[tid] = g_ce[tid]; }
    __syncthreads();
    if (tid < 128) {
        int k = tid >> 3, r = tid & 7;
        embT[k * 8 + r] = embr[r * 16 + k];
        xv[(8 + k) * 8 + r] = embr[r * 16 + k];   // constant emb part of in0
    }

    // LSTM GEMM map
    const int g0  = (tid >> 2) << 2;   // gate offset (quads share weight)
    const int r0g = (tid & 3) << 1;    // 2 rows per thread
    // combine / diffusion maps
    const int uu  = tid & 127;
    const int rq  = tid >> 7;          // 0..3 -> rows 2rq, 2rq+1

    float c0r[2] = {0.f, 0.f};
    float c1r[2] = {0.f, 0.f};

    // prime staging pipeline: stream chunks 0 (buf0), 1 (buf1)
    stage_stream(0, stg);
    stage_stream(1, stg + KC * 512);
    int par = 0;   // buffer of next chunk to compute

    // =================== LSTM encoder ===================
    for (int t = 0; t < 96; t++) {
        if (tid < 64) {                 // in0 rows 0..7 ([k][r])
            int k = tid & 7, r = tid >> 3;
            xv[k * 8 + r] = __ldg(&x_hist[((brow + r) * 96 + t) * 8 + k]);
        }

        ull a00 = 0, a01 = 0, a10 = 0, a11 = 0;
        #pragma unroll 1
        for (int c = 0; c < 13; c++) {
            asm volatile("cp.async.wait_group 1;\n" ::: "memory");
            __syncthreads();

            const float* buf = stg + par * (KC * 512);
            const int layer = (c < 5) ? 0 : 1;
            const int kb = layer ? (c - 5) * KC : c * KC;
            const int kc = (c == 4) ? 24 : KC;
            const float* xb = layer ? (xv + 192) : xv;

            #pragma unroll 8
            for (int kk = 0; kk < kc; kk++) {
                const ulonglong2 w = *reinterpret_cast<const ulonglong2*>(buf + (kk << 9) + g0);
                const float2 x = *reinterpret_cast<const float2*>(xb + ((kb + kk) << 3) + r0g);
                ull d0 = dup2(x.x), d1 = dup2(x.y);
                ffma2(a00, w.x, d0); ffma2(a01, w.y, d0);
                ffma2(a10, w.x, d1); ffma2(a11, w.y, d1);
            }

            if (c == 4 || c == 12) {
                *reinterpret_cast<ulonglong2*>(&gates[(r0g    ) * 512 + g0]) = make_ulonglong2(a00, a01);
                *reinterpret_cast<ulonglong2*>(&gates[(r0g + 1) * 512 + g0]) = make_ulonglong2(a10, a11);
            }
            __syncthreads();

            // stage chunk c+2 (wraps into next step) into the buffer just consumed
            {
                int s = c + 2; if (s >= 13) s -= 13;
                stage_stream(s, stg + par * (KC * 512));
            }
            par ^= 1;

            if (c == 4) {
                // combine layer 0 -> h0 (xv rows 24..151)
                a00 = a01 = a10 = a11 = 0;   // reset for layer 1
                #pragma unroll
                for (int ri = 0; ri < 2; ri++) {
                    int r = rq * 2 + ri;
                    float gi = gates[r * 512 + uu]       + b0s[uu];
                    float gf = gates[r * 512 + 128 + uu] + b0s[128 + uu];
                    float gc = gates[r * 512 + 256 + uu] + b0s[256 + uu];
                    float go = gates[r * 512 + 384 + uu] + b0s[384 + uu];
                    float cc = sigf(gf) * c0r[ri] + sigf(gi) * tanhf_fast(gc);
                    c0r[ri] = cc;
                    xv[(24 + uu) * 8 + r] = sigf(go) * tanhf_fast(cc);
                }
            } else if (c == 12) {
                // combine layer 1 -> h1 (xv rows 152..279)
                a00 = a01 = a10 = a11 = 0;
                #pragma unroll
                for (int ri = 0; ri < 2; ri++) {
                    int r = rq * 2 + ri;
                    float gi = gates[r * 512 + uu]       + b1s[uu];
                    float gf = gates[r * 512 + 128 + uu] + b1s[128 + uu];
                    float gc = gates[r * 512 + 256 + uu] + b1s[256 + uu];
                    float go = gates[r * 512 + 384 + uu] + b1s[384 + uu];
                    float cc = sigf(gf) * c1r[ri] + sigf(gi) * tanhf_fast(gc);
                    c1r[ri] = cc;
                    xv[(152 + uu) * 8 + r] = sigf(go) * tanhf_fast(cc);
                }
            }
        }
    }
    __syncthreads();
    // enc_out = xv rows 152..279, layout [128][8]

    // =================== AR + diffusion ===================
    const float b3v = __ldg(&b3p[0]);

    // stage-2 map: v = tid>>2 (output unit), us = tid&3 (u-split); u = 4*i + us
    const int v  = tid >> 2;
    const int us = tid & 3;
    float w2r[32];
    #pragma unroll
    for (int i = 0; i < 32; i++) w2r[i] = __ldg(&g_W2s[((4 * i + us) << 7) + v]);
    const float w3v  = __ldg(&W3[v]);
    const float bm2v = __ldg(&b2m[v]);
    const int wid  = tid >> 5;
    const int lane = tid & 31;

    // stage-1 per-thread constants (map: uu, rq)
    const float w1yv = __ldg(&g_W1T[151 * 128 + uu]);

    // prev_y per thread for its 2 rows
    float2 ypa;
    ypa.x = __ldg(&y0[brow + rq * 2]);
    ypa.y = __ldg(&y0[brow + rq * 2 + 1]);

    for (int p = 0; p < 8; p++) {
        if (tid < 48) {                 // xfT[k][8r]
            int k = tid / 8, r = tid & 7;
            xfT[k * 8 + r] = __ldg(&x_future[(brow + r) * 48 + p * 6 + k]);
        }
        if (tid < 16) {
            int j = tid & 7;
            float f = __expf(-logf(10000.0f) * (float)j / 8.0f);
            float a = (float)p * f;
            hes[tid] = (tid < 8) ? cosf(a) : sinf(a);
        }
        float2 yr;
        yr.x = __ldg(&init_noise[p * 1024 + brow + rq * 2]);
        yr.y = __ldg(&init_noise[p * 1024 + brow + rq * 2 + 1]);
        __syncthreads();

        // ---- base[uu][2 rows] in registers ----
        float2 base = make_float2(0.f, 0.f);
        {
            #pragma unroll 8
            for (int k = 0; k < 128; k++) {
                float w = __ldg(&g_W1T[(k << 7) + uu]);
                const float2 h = *reinterpret_cast<const float2*>(&xv[(152 + k) * 8 + rq * 2]);
                base.x += w * h.x; base.y += w * h.y;
            }
            #pragma unroll
            for (int k = 0; k < 6; k++) {
                float w = __ldg(&g_W1T[((128 + k) << 7) + uu]);
                const float2 x = *reinterpret_cast<const float2*>(&xfT[k * 8 + rq * 2]);
                base.x += w * x.x; base.y += w * x.y;
            }
            #pragma unroll
            for (int k = 0; k < 16; k++) {
                float w = __ldg(&g_W1T[((134 + k) << 7) + uu]);
                const float2 e = *reinterpret_cast<const float2*>(&embT[k * 8 + rq * 2]);
                base.x += w * e.x; base.y += w * e.y;
            }
            {
                float w = __ldg(&g_W1T[(150 << 7) + uu]);
                base.x += w * ypa.x; base.y += w * ypa.y;
            }
            float hsum = 0.f;
            #pragma unroll
            for (int k = 0; k < 16; k++) hsum += __ldg(&g_W1T[((168 + k) << 7) + uu]) * hes[k];
            float bb = __ldg(&b1m[uu]) + hsum;
            base.x += bb; base.y += bb;
        }

        // ---- 100 diffusion steps ----
        for (int tt = 99; tt >= 0; tt--) {
            // stage 1: mh1[uu][2 rows]
            {
                float av = a1s[tt * 128 + uu];
                float2 m;
                m.x = fmaxf(base.x + yr.x * w1yv + av, 0.f);
                m.y = fmaxf(base.y + yr.y * w1yv + av, 0.f);
                *reinterpret_cast<float2*>(&mh1[(uu << 3) + rq * 2]) = m;
            }
            __syncthreads();   // A: mh1 ready

            // stage 2: partial GEMV over u = 4i+us, all 8 rows
            float h2[8];
            {
                ull acc0, acc1, acc2, acc3;
                if (us == 0) { acc0 = pack2(bm2v, bm2v); acc1 = acc0; acc2 = acc0; acc3 = acc0; }
                else         { acc0 = acc1 = acc2 = acc3 = 0ULL; }
                #pragma unroll 8
                for (int i = 0; i < 32; i++) {
                    const int u = 4 * i + us;
                    const ulonglong2 hA = *reinterpret_cast<const ulonglong2*>(&mh1[u << 3]);
                    const ulonglong2 hB = *reinterpret_cast<const ulonglong2*>(&mh1[(u << 3) + 4]);
                    ull dw = dup2(w2r[i]);
                    ffma2(acc0, dw, hA.x); ffma2(acc1, dw, hA.y);
                    ffma2(acc2, dw, hB.x); ffma2(acc3, dw, hB.y);
                }
                float2 f0 = unpack2(acc0), f1 = unpack2(acc1), f2 = unpack2(acc2), f3 = unpack2(acc3);
                h2[0] = f0.x; h2[1] = f0.y; h2[2] = f1.x; h2[3] = f1.y;
                h2[4] = f2.x; h2[5] = f2.y; h2[6] = f3.x; h2[7] = f3.y;
            }
            // reduce over us (lanes +1, +2), then relu*w3, then over v-in-warp (+4,+8,+16)
            #pragma unroll
            for (int j = 0; j < 8; j++) {
                h2[j] += __shfl_down_sync(0xffffffffu, h2[j], 1);
                h2[j] += __shfl_down_sync(0xffffffffu, h2[j], 2);
                h2[j] = fmaxf(h2[j], 0.f) * w3v;
                h2[j] += __shfl_down_sync(0xffffffffu, h2[j], 4);
                h2[j] += __shfl_down_sync(0xffffffffu, h2[j], 8);
                h2[j] += __shfl_down_sync(0xffffffffu, h2[j], 16);
            }
            if (lane == 0) {
                *reinterpret_cast<float4*>(&wpart[wid * 8])     = make_float4(h2[0], h2[1], h2[2], h2[3]);
                *reinterpret_cast<float4*>(&wpart[wid * 8 + 4]) = make_float4(h2[4], h2[5], h2[6], h2[7]);
            }
            __syncthreads();   // B: warp partials ready, mh1 consumed

            // eps + y update (redundant per thread, registers)
            {
                float sx = 0.f, sy = 0.f;
                #pragma unroll
                for (int w = 0; w < 16; w++) {
                    const float2 q = *reinterpret_cast<const float2*>(&wpart[w * 8 + rq * 2]);
                    sx += q.x; sy += q.y;
                }
                float cy = cys[tt], ce = ces[tt];
                yr.x = cy * yr.x - ce * (b3v + sx);
                yr.y = cy * yr.y - ce * (b3v + sy);
            }
        }

        if ((tid & 127) == 0) {   // u==0 threads: one per row pair
            out[(brow + rq * 2    ) * 8 + p] = yr.x;
            out[(brow + rq * 2 + 1) * 8 + p] = yr.y;
        }
        ypa = yr;
        __syncthreads();   // protect xfT/hes rewrite next AR step
    }
}

// ---------------- launch ----------------
extern "C" void kernel_launch(void* const* d_in, const int* in_sizes, int n_in,
                              void* d_out, int out_size) {
    const float* x_hist     = (const float*)d_in[0];
    const float* x_future   = (const float*)d_in[1];
    const float* y0         = (const float*)d_in[2];
    const int*   turb_idx   = (const int*)d_in[3];
    const float* init_noise = (const float*)d_in[5];
    const float* turb_emb   = (const float*)d_in[6];
    const float* W_ih0      = (const float*)d_in[7];
    const float* W_hh0      = (const float*)d_in[8];
    const float* b_ih0      = (const float*)d_in[9];
    const float* b_hh0      = (const float*)d_in[10];
    const float* W_ih1      = (const float*)d_in[11];
    const float* W_hh1      = (const float*)d_in[12];
    const float* b_ih1      = (const float*)d_in[13];
    const float* b_hh1      = (const float*)d_in[14];
    const float* W1         = (const float*)d_in[15];
    const float* b1m        = (const float*)d_in[16];
    const float* W2         = (const float*)d_in[17];
    const float* b2m        = (const float*)d_in[18];
    const float* W3         = (const float*)d_in[19];
    const float* b3         = (const float*)d_in[20];
    float* out = (float*)d_out;

    prologue_kernel<<<128, 256>>>(W_ih0, W_hh0, b_ih0, b_hh0,
                                  W_ih1, W_hh1, b_ih1, b_hh1, W1, W2);

    cudaFuncSetAttribute(fused_kernel, cudaFuncAttributeMaxDynamicSharedMemorySize, SMEM_BYTES);
    fused_kernel<<<NBLK, NT, SMEM_BYTES>>>(x_hist, x_future, y0, turb_idx, init_noise,
                                           turb_emb, b1m, b2m, W3, b3, out);
}

// round 6
// speedup vs baseline: 1.5965x; 1.5965x over previous
#include <cuda_runtime.h>
#include <math.h>

#define NT 256
#define RPB 8
#define NBLK 128
#define KC 32

typedef unsigned long long ull;

// ---------------- device scratch ----------------
__device__ float g_W0cat[152 * 512];   // [k][g]: rows 0..23 Wih0^T, 24..151 Whh0^T
__device__ float g_W1cat[256 * 512];   // [k][g]: rows 0..127 Wih1^T, 128..255 Whh1^T
__device__ float g_b0[512];
__device__ float g_b1[512];
__device__ float g_W1T[184 * 128];     // [k][u]
__device__ float g_W2s[128 * 128];     // [u][v] = W2[v][u]
__device__ float g_A1t[100 * 128];
__device__ float g_cy[100];
__device__ float g_ce[100];

// ---------------- prologue ----------------
__global__ void prologue_kernel(const float* __restrict__ W_ih0, const float* __restrict__ W_hh0,
                                const float* __restrict__ b_ih0, const float* __restrict__ b_hh0,
                                const float* __restrict__ W_ih1, const float* __restrict__ W_hh1,
                                const float* __restrict__ b_ih1, const float* __restrict__ b_hh1,
                                const float* __restrict__ W1,    const float* __restrict__ W2) {
    int tid = blockIdx.x * blockDim.x + threadIdx.x;
    int nth = gridDim.x * blockDim.x;

    for (int i = tid; i < 24 * 512; i += nth) {
        int k = i >> 9, g = i & 511;
        g_W0cat[i] = W_ih0[g * 24 + k];
    }
    for (int i = tid; i < 128 * 512; i += nth) {
        int k = i >> 9, g = i & 511;
        g_W0cat[(24 + k) * 512 + g]  = W_hh0[g * 128 + k];
        g_W1cat[k * 512 + g]         = W_ih1[g * 128 + k];
        g_W1cat[(128 + k) * 512 + g] = W_hh1[g * 128 + k];
    }
    for (int i = tid; i < 512; i += nth) {
        g_b0[i] = b_ih0[i] + b_hh0[i];
        g_b1[i] = b_ih1[i] + b_hh1[i];
    }
    for (int i = tid; i < 184 * 128; i += nth) {
        int k = i >> 7, u = i & 127;
        g_W1T[i] = W1[u * 184 + k];
    }
    for (int i = tid; i < 128 * 128; i += nth) {
        int u = i >> 7, v = i & 127;
        g_W2s[i] = W2[v * 128 + u];
    }
    for (int i = tid; i < 100 * 128; i += nth) {
        int t = i >> 7, u = i & 127;
        float acc = 0.f;
        #pragma unroll
        for (int j = 0; j < 8; j++) {
            float f = expf(-logf(10000.0f) * (float)j / 8.0f);
            float a = (float)t * f;
            acc += W1[u * 184 + 152 + j] * cosf(a);
            acc += W1[u * 184 + 160 + j] * sinf(a);
        }
        g_A1t[i] = acc;
    }
    if (tid == 0) {
        float ab = 1.0f;
        for (int t = 0; t < 100; t++) {
            float beta  = 1e-4f + (0.02f - 1e-4f) * (float)t / 99.0f;
            float alpha = 1.0f - beta;
            ab *= alpha;
            if (t == 0) {
                float p = sqrtf(ab) + 1e-8f;
                g_cy[0] = 1.0f / p;
                g_ce[0] = sqrtf(1.0f - ab) / p;
            } else {
                float inv = 1.0f / (sqrtf(alpha) + 1e-8f);
                g_cy[t] = inv;
                g_ce[t] = beta / (sqrtf(1.0f - ab) + 1e-8f) * inv;
            }
        }
    }
}

// ---------------- fast math helpers ----------------
__device__ __forceinline__ float sigf(float x) {
    float xc = fminf(fmaxf(x, -30.f), 30.f);
    return __fdividef(1.0f, 1.0f + __expf(-xc));
}
__device__ __forceinline__ float tanhf_fast(float x) {
    float xc = fminf(fmaxf(x, -15.f), 15.f);
    float e = __expf(2.0f * xc);
    return __fdividef(e - 1.0f, e + 1.0f);
}
__device__ __forceinline__ void ffma2(ull &d, ull a, ull b) {
    asm("fma.rn.f32x2 %0, %1, %2, %0;" : "+l"(d) : "l"(a), "l"(b));
}
__device__ __forceinline__ ull dup2(float x) {
    ull r;
    asm("mov.b64 %0, {%1, %1};" : "=l"(r) : "f"(x));
    return r;
}
__device__ __forceinline__ ull pack2(float lo, float hi) {
    ull r;
    asm("mov.b64 %0, {%1, %2};" : "=l"(r) : "f"(lo), "f"(hi));
    return r;
}
__device__ __forceinline__ float2 unpack2(ull v) {
    float2 r;
    asm("mov.b64 {%0, %1}, %2;" : "=f"(r.x), "=f"(r.y) : "l"(v));
    return r;
}

// ---------------- smem layout (floats) ----------------
// xv2: duplicated activations: value of (row, r) stored at xv2[(row*8+r)*2] and +1.
// rows 0..7 x_t, 8..23 emb, 24..151 h0, 152..279 h1
#define SM_XV2    0        // 280*16 = 4480
#define SM_GATES  4480     // [8][512] = 4096
#define SM_STAGE  8576     // 2 x (KC*512) = 32768
#define SM_B0     41344    // 512
#define SM_B1     41856    // 512
#define SM_EMBR   42368    // [8][16] = 128
#define SM_EMBT   42496    // [16][8] = 128
#define SM_MH1    42624    // [128][8] = 1024
#define SM_A1     43648    // 12800
#define SM_W1Y    56448    // 128
#define SM_W3     56576    // 128
#define SM_BM2    56704    // 128
#define SM_XFT    56832    // 48
#define SM_HES    56880    // 32
#define SM_CY     56912    // 100
#define SM_CE     57012    // 100
#define SM_RED    57112    // 32
#define SM_TOTAL  57144
#define SMEM_BYTES (SM_TOTAL * 4)

// ---------------- staging helper ----------------
__device__ __forceinline__ void stage_chunk(float* sdst, const float* __restrict__ gsrc, int nf4) {
    unsigned sbase = (unsigned)__cvta_generic_to_shared(sdst);
    for (int i = threadIdx.x; i < nf4; i += NT) {
        asm volatile("cp.async.cg.shared.global [%0], [%1], 16;\n"
                     :: "r"(sbase + i * 16), "l"(gsrc + i * 4));
    }
    asm volatile("cp.async.commit_group;\n" ::: "memory");
}

__device__ __forceinline__ void barh(int half) {
    asm volatile("bar.sync %0, 128;" :: "r"(half + 1) : "memory");
}

// ---------------- LSTM GEMM: f32x2, paired-lane weights, pre-duplicated x ----------------
__device__ __forceinline__ void lstm_gemm(const float* __restrict__ gW, int K,
                                          const float* __restrict__ xv2, float* gates,
                                          float* stg, int g0, int r0g) {
    ull a00 = 0, a01 = 0, a10 = 0, a11 = 0, a20 = 0, a21 = 0, a30 = 0, a31 = 0;

    const int NC = (K + KC - 1) / KC;
    {
        int kc0 = (K < KC) ? K : KC;
        stage_chunk(stg, gW, kc0 * 128);
        if (NC > 1) {
            int kc1 = (K - KC < KC) ? (K - KC) : KC;
            stage_chunk(stg + KC * 512, gW + KC * 512, kc1 * 128);
        }
    }

    for (int c = 0; c < NC; c++) {
        if (c + 1 < NC) asm volatile("cp.async.wait_group 1;\n" ::: "memory");
        else            asm volatile("cp.async.wait_group 0;\n" ::: "memory");
        __syncthreads();

        const float* buf = stg + (c & 1) * (KC * 512);
        const int kbase = c * KC;
        int kc = K - kbase; if (kc > KC) kc = KC;

        #pragma unroll 8
        for (int kk = 0; kk < kc; kk++) {
            const ulonglong2 w = *reinterpret_cast<const ulonglong2*>(buf + (kk << 9) + g0);
            const float* xp = xv2 + ((kbase + kk) << 4) + (r0g << 1);
            const ulonglong2 xa = *reinterpret_cast<const ulonglong2*>(xp);
            const ulonglong2 xb = *reinterpret_cast<const ulonglong2*>(xp + 4);
            ffma2(a00, w.x, xa.x); ffma2(a01, w.y, xa.x);
            ffma2(a10, w.x, xa.y); ffma2(a11, w.y, xa.y);
            ffma2(a20, w.x, xb.x); ffma2(a21, w.y, xb.x);
            ffma2(a30, w.x, xb.y); ffma2(a31, w.y, xb.y);
        }

        if (c == NC - 1) {
            *reinterpret_cast<ulonglong2*>(&gates[(r0g    ) * 512 + g0]) = make_ulonglong2(a00, a01);
            *reinterpret_cast<ulonglong2*>(&gates[(r0g + 1) * 512 + g0]) = make_ulonglong2(a10, a11);
            *reinterpret_cast<ulonglong2*>(&gates[(r0g + 2) * 512 + g0]) = make_ulonglong2(a20, a21);
            *reinterpret_cast<ulonglong2*>(&gates[(r0g + 3) * 512 + g0]) = make_ulonglong2(a30, a31);
        }
        __syncthreads();

        if (c + 2 < NC) {
            int kn = K - (c + 2) * KC; if (kn > KC) kn = KC;
            stage_chunk(stg + (c & 1) * (KC * 512), gW + (c + 2) * KC * 512, kn * 128);
        }
    }
}

// ---------------- main fused kernel ----------------
__global__ __launch_bounds__(NT, 1)
void fused_kernel(const float* __restrict__ x_hist, const float* __restrict__ x_future,
                  const float* __restrict__ y0, const int* __restrict__ turb_idx,
                  const float* __restrict__ init_noise, const float* __restrict__ turb_emb,
                  const float* __restrict__ b1m, const float* __restrict__ b2m,
                  const float* __restrict__ W3, const float* __restrict__ b3p,
                  float* __restrict__ out) {
    extern __shared__ float sm[];
    float* xv2   = sm + SM_XV2;
    float* gates = sm + SM_GATES;
    float* stg   = sm + SM_STAGE;
    float* b0s   = sm + SM_B0;
    float* b1s   = sm + SM_B1;
    float* embr  = sm + SM_EMBR;
    float* embT  = sm + SM_EMBT;
    float* mh1   = sm + SM_MH1;
    float* a1s   = sm + SM_A1;
    float* w1ys  = sm + SM_W1Y;
    float* w3s   = sm + SM_W3;
    float* bm2s  = sm + SM_BM2;
    float* xfT   = sm + SM_XFT;
    float* hes   = sm + SM_HES;
    float* cys   = sm + SM_CY;
    float* ces   = sm + SM_CE;
    float* red   = sm + SM_RED;

    const int tid  = threadIdx.x;
    const int brow = blockIdx.x * RPB;

    // ---- init ----
    for (int i = tid; i < 4480; i += NT) xv2[i] = 0.0f;
    for (int i = tid; i < 512; i += NT) { b0s[i] = g_b0[i]; b1s[i] = g_b1[i]; }
    for (int i = tid; i < 12800; i += NT) a1s[i] = g_A1t[i];
    if (tid < 128) {
        int r = tid >> 4, k = tid & 15;
        embr[r * 16 + k] = turb_emb[turb_idx[brow + r] * 16 + k];
    }
    if (tid < 128) {
        w1ys[tid] = g_W1T[151 * 128 + tid];
        w3s[tid]  = W3[tid];
        bm2s[tid] = b2m[tid];
    }
    if (tid < 100) { cys[tid] = g_cy[tid]; ces[tid] = g_ce[tid]; }
    __syncthreads();
    if (tid < 128) {
        int k = tid >> 3, r = tid & 7;
        float v = embr[r * 16 + k];
        embT[k * 8 + r] = v;
        *reinterpret_cast<ull*>(&xv2[(((8 + k) << 3) + r) << 1]) = pack2(v, v);
    }

    const int g0  = (tid >> 1) << 2;
    const int r0g = (tid & 1) << 2;
    const int uu  = tid & 127;
    const int r0c = (tid >> 7) << 2;

    float c0r[4] = {0.f, 0.f, 0.f, 0.f};
    float c1r[4] = {0.f, 0.f, 0.f, 0.f};

    // =================== LSTM encoder ===================
    for (int t = 0; t < 96; t++) {
        if (tid < 64) {
            int k = tid & 7, r = tid >> 3;
            float v = __ldg(&x_hist[((brow + r) * 96 + t) * 8 + k]);
            *reinterpret_cast<ull*>(&xv2[((k << 3) + r) << 1]) = pack2(v, v);
        }
        lstm_gemm(g_W0cat, 152, xv2, gates, stg, g0, r0g);
        #pragma unroll
        for (int ri = 0; ri < 4; ri++) {
            int r = r0c + ri;
            float gi = gates[r * 512 + uu]       + b0s[uu];
            float gf = gates[r * 512 + 128 + uu] + b0s[128 + uu];
            float gc = gates[r * 512 + 256 + uu] + b0s[256 + uu];
            float go = gates[r * 512 + 384 + uu] + b0s[384 + uu];
            float cc = sigf(gf) * c0r[ri] + sigf(gi) * tanhf_fast(gc);
            c0r[ri] = cc;
            float hv = sigf(go) * tanhf_fast(cc);
            *reinterpret_cast<ull*>(&xv2[(((24 + uu) << 3) + r) << 1]) = pack2(hv, hv);
        }
        lstm_gemm(g_W1cat, 256, xv2 + 24 * 16, gates, stg, g0, r0g);
        #pragma unroll
        for (int ri = 0; ri < 4; ri++) {
            int r = r0c + ri;
            float gi = gates[r * 512 + uu]       + b1s[uu];
            float gf = gates[r * 512 + 128 + uu] + b1s[128 + uu];
            float gc = gates[r * 512 + 256 + uu] + b1s[256 + uu];
            float go = gates[r * 512 + 384 + uu] + b1s[384 + uu];
            float cc = sigf(gf) * c1r[ri] + sigf(gi) * tanhf_fast(gc);
            c1r[ri] = cc;
            float hv = sigf(go) * tanhf_fast(cc);
            *reinterpret_cast<ull*>(&xv2[(((152 + uu) << 3) + r) << 1]) = pack2(hv, hv);
        }
        __syncthreads();
    }
    __syncthreads();

    // =================== AR + diffusion (two independent halves) ===================
    const int half = tid >> 7;
    const int local = tid & 127;
    const int r0d = half * 4;
    const float b3v = __ldg(&b3p[0]);

    float w2r[128];
    #pragma unroll
    for (int u = 0; u < 128; u++) w2r[u] = __ldg(&g_W2s[(u << 7) + uu]);

    const float w1yv = w1ys[uu];
    const float w3v  = w3s[uu];
    const float bm2v = bm2s[uu];

    float ypa[4];
    #pragma unroll
    for (int j = 0; j < 4; j++) ypa[j] = __ldg(&y0[brow + r0d + j]);

    const int wih = (tid >> 5) & 3;
    const int lane = tid & 31;

    for (int p = 0; p < 8; p++) {
        if (local < 24) {
            int k = local >> 2, rl = local & 3;
            xfT[half * 24 + k * 4 + rl] = __ldg(&x_future[(brow + r0d + rl) * 48 + p * 6 + k]);
        }
        if (local < 16) {
            int j = local & 7;
            float f = __expf(-logf(10000.0f) * (float)j / 8.0f);
            float a = (float)p * f;
            hes[half * 16 + local] = (local < 8) ? cosf(a) : sinf(a);
        }
        float yra[4];
        #pragma unroll
        for (int j = 0; j < 4; j++) yra[j] = __ldg(&init_noise[p * 1024 + brow + r0d + j]);
        barh(half);

        float4 base = make_float4(0.f, 0.f, 0.f, 0.f);
        {
            #pragma unroll 8
            for (int k = 0; k < 128; k++) {
                float w = __ldg(&g_W1T[(k << 7) + uu]);
                const float* hp = &xv2[(((152 + k) << 3) + r0d) << 1];
                base.x += w * hp[0]; base.y += w * hp[2];
                base.z += w * hp[4]; base.w += w * hp[6];
            }
            #pragma unroll
            for (int k = 0; k < 6; k++) {
                float w = __ldg(&g_W1T[((128 + k) << 7) + uu]);
                const float4 x = *reinterpret_cast<const float4*>(&xfT[half * 24 + k * 4]);
                base.x += w * x.x; base.y += w * x.y; base.z += w * x.z; base.w += w * x.w;
            }
            #pragma unroll
            for (int k = 0; k < 16; k++) {
                float w = __ldg(&g_W1T[((134 + k) << 7) + uu]);
                const float* ep = &embT[k * 8 + r0d];
                base.x += w * ep[0]; base.y += w * ep[1]; base.z += w * ep[2]; base.w += w * ep[3];
            }
            {
                float w = __ldg(&g_W1T[(150 << 7) + uu]);
                base.x += w * ypa[0]; base.y += w * ypa[1]; base.z += w * ypa[2]; base.w += w * ypa[3];
            }
            float hsum = 0.f;
            #pragma unroll
            for (int k = 0; k < 16; k++) hsum += __ldg(&g_W1T[((168 + k) << 7) + uu]) * hes[half * 16 + k];
            float bb = __ldg(&b1m[uu]) + hsum;
            base.x += bb; base.y += bb; base.z += bb; base.w += bb;
        }

        for (int tt = 99; tt >= 0; tt--) {
            {
                float av = a1s[tt * 128 + uu];
                float4 m;
                m.x = fmaxf(base.x + yra[0] * w1yv + av, 0.f);
                m.y = fmaxf(base.y + yra[1] * w1yv + av, 0.f);
                m.z = fmaxf(base.z + yra[2] * w1yv + av, 0.f);
                m.w = fmaxf(base.w + yra[3] * w1yv + av, 0.f);
                *reinterpret_cast<float4*>(&mh1[(uu << 3) + r0d]) = m;
            }
            barh(half);

            {
                ull acc01 = pack2(bm2v, bm2v);
                ull acc23 = acc01;
                #pragma unroll
                for (int u = 0; u < 128; u++) {
                    const ulonglong2 h = *reinterpret_cast<const ulonglong2*>(&mh1[(u << 3) + r0d]);
                    ull dw = dup2(w2r[u]);
                    ffma2(acc01, dw, h.x);
                    ffma2(acc23, dw, h.y);
                }
                float2 a01 = unpack2(acc01);
                float2 a23 = unpack2(acc23);
                float e0 = fmaxf(a01.x, 0.f) * w3v;
                float e1 = fmaxf(a01.y, 0.f) * w3v;
                float e2 = fmaxf(a23.x, 0.f) * w3v;
                float e3 = fmaxf(a23.y, 0.f) * w3v;
                #pragma unroll
                for (int off = 16; off > 0; off >>= 1) {
                    e0 += __shfl_down_sync(0xffffffffu, e0, off);
                    e1 += __shfl_down_sync(0xffffffffu, e1, off);
                    e2 += __shfl_down_sync(0xffffffffu, e2, off);
                    e3 += __shfl_down_sync(0xffffffffu, e3, off);
                }
                if (lane == 0)
                    *reinterpret_cast<float4*>(&red[half * 16 + wih * 4]) = make_float4(e0, e1, e2, e3);
            }
            barh(half);

            {
                const float4 q0 = *reinterpret_cast<const float4*>(&red[half * 16 + 0]);
                const float4 q1 = *reinterpret_cast<const float4*>(&red[half * 16 + 4]);
                const float4 q2 = *reinterpret_cast<const float4*>(&red[half * 16 + 8]);
                const float4 q3 = *reinterpret_cast<const float4*>(&red[half * 16 + 12]);
                float cy = cys[tt], ce = ces[tt];
                yra[0] = cy * yra[0] - ce * (b3v + q0.x + q1.x + q2.x + q3.x);
                yra[1] = cy * yra[1] - ce * (b3v + q0.y + q1.y + q2.y + q3.y);
                yra[2] = cy * yra[2] - ce * (b3v + q0.z + q1.z + q2.z + q3.z);
                yra[3] = cy * yra[3] - ce * (b3v + q0.w + q1.w + q2.w + q3.w);
            }
        }

        if (local < 4) {
            float v = (local == 0) ? yra[0] : (local == 1) ? yra[1] : (local == 2) ? yra[2] : yra[3];
            out[(brow + r0d + local) * 8 + p] = v;
        }
        #pragma unroll
        for (int j = 0; j < 4; j++) ypa[j] = yra[j];
    }
}

// ---------------- launch ----------------
extern "C" void kernel_launch(void* const* d_in, const int* in_sizes, int n_in,
                              void* d_out, int out_size) {
    const float* x_hist     = (const float*)d_in[0];
    const float* x_future   = (const float*)d_in[1];
    const float* y0         = (const float*)d_in[2];
    const int*   turb_idx   = (const int*)d_in[3];
    const float* init_noise = (const float*)d_in[5];
    const float* turb_emb   = (const float*)d_in[6];
    const float* W_ih0      = (const float*)d_in[7];
    const float* W_hh0      = (const float*)d_in[8];
    const float* b_ih0      = (const float*)d_in[9];
    const float* b_hh0      = (const float*)d_in[10];
    const float* W_ih1      = (const float*)d_in[11];
    const float* W_hh1      = (const float*)d_in[12];
    const float* b_ih1      = (const float*)d_in[13];
    const float* b_hh1      = (const float*)d_in[14];
    const float* W1         = (const float*)d_in[15];
    const float* b1m        = (const float*)d_in[16];
    const float* W2         = (const float*)d_in[17];
    const float* b2m        = (const float*)d_in[18];
    const float* W3         = (const float*)d_in[19];
    const float* b3         = (const float*)d_in[20];
    float* out = (float*)d_out;

    prologue_kernel<<<128, 256>>>(W_ih0, W_hh0, b_ih0, b_hh0,
                                  W_ih1, W_hh1, b_ih1, b_hh1, W1, W2);

    cudaFuncSetAttribute(fused_kernel, cudaFuncAttributeMaxDynamicSharedMemorySize, SMEM_BYTES);
    fused_kernel<<<NBLK, NT, SMEM_BYTES>>>(x_hist, x_future, y0, turb_idx, init_noise,
                                           turb_emb, b1m, b2m, W3, b3, out);
}